// round 1
// baseline (speedup 1.0000x reference)
#include <cuda_runtime.h>
#include <cstdint>

#define BATCH 8192
#define IN    2048
#define OUT   2048
#define P     8

#define BM 128
#define BN 128
#define BK 16

// Routing scratch (device globals: no allocation allowed)
__device__ int g_cnt[P];
__device__ int g_list[P][BATCH];

__global__ void zero_counts_kernel() {
    if (threadIdx.x < P) g_cnt[threadIdx.x] = 0;
}

// ---------------------------------------------------------------------------
// Selector: logits = x @ Ws^T + bs ; top-2 (softmax is monotone -> skip it).
// One warp per sample. Ws (64KB) stays hot in L1/L2.
// Builds per-expert compacted sample lists via atomics. List order is
// nondeterministic but final values are order-independent (see epilogue).
// ---------------------------------------------------------------------------
__global__ void selector_kernel(const float* __restrict__ x,
                                const float* __restrict__ Ws,
                                const float* __restrict__ bs) {
    int warp = threadIdx.x >> 5;
    int lane = threadIdx.x & 31;
    int warps_per_grid = (blockDim.x >> 5) * gridDim.x;
    for (int s = blockIdx.x * (blockDim.x >> 5) + warp; s < BATCH; s += warps_per_grid) {
        const float4* xr = (const float4*)(x + (size_t)s * IN);
        float acc[P];
#pragma unroll
        for (int p = 0; p < P; p++) acc[p] = 0.f;
        for (int k4 = lane; k4 < IN / 4; k4 += 32) {
            float4 xv = xr[k4];
#pragma unroll
            for (int p = 0; p < P; p++) {
                float4 wv = ((const float4*)(Ws + (size_t)p * IN))[k4];
                acc[p] += xv.x * wv.x + xv.y * wv.y + xv.z * wv.z + xv.w * wv.w;
            }
        }
#pragma unroll
        for (int p = 0; p < P; p++) {
#pragma unroll
            for (int off = 16; off; off >>= 1)
                acc[p] += __shfl_xor_sync(0xffffffffu, acc[p], off);
        }
        if (lane == 0) {
            float best = -1e30f; int e1 = 0;
#pragma unroll
            for (int p = 0; p < P; p++) {
                float v = acc[p] + bs[p];
                acc[p] = v;
                if (v > best) { best = v; e1 = p; }   // ties -> lowest index (matches top_k)
            }
            float sec = -1e30f; int e2 = 0;
#pragma unroll
            for (int p = 0; p < P; p++) {
                if (p != e1 && acc[p] > sec) { sec = acc[p]; e2 = p; }
            }
            int p1 = atomicAdd(&g_cnt[e1], 1);
            g_list[e1][p1] = s;
            int p2 = atomicAdd(&g_cnt[e2], 1);
            g_list[e2][p2] = s;
        }
    }
}

// ---------------------------------------------------------------------------
// Grouped gather-GEMM: for expert e, Y = X[rows_e] @ W[e]^T ; epilogue does
// atomicAdd(out[row], 0.5*(y + b[e])). Each out element receives exactly two
// fp32 atomic adds into a zeroed buffer -> bitwise deterministic (a+b == b+a).
//
// 128x128x16 tiles, 256 threads, 8x8 microtile computed with packed
// fma.rn.f32x2 (FFMA2) -> 2x the fp32 FMA rate of plain FFMA on sm_103a.
// ---------------------------------------------------------------------------
__global__ __launch_bounds__(256, 2)
void moe_gemm_kernel(const float* __restrict__ x,
                     const float* __restrict__ W,
                     const float* __restrict__ bias,
                     float* __restrict__ out) {
    const int e = blockIdx.z;
    const int n_rows = g_cnt[e];
    const int row0 = blockIdx.y * BM;
    if (row0 >= n_rows) return;
    const int col0 = blockIdx.x * BN;

    __shared__ float As[BK][BM];   // A^T tile (k-major)
    __shared__ float Bs[BK][BN];   // W[e] tile transposed: Bs[k][n] = W[e][col0+n][k0+k]
    __shared__ int   ridx[BM];

    const int tid = threadIdx.x;
    if (tid < BM) {
        int r = row0 + tid;
        ridx[tid] = (r < n_rows) ? g_list[e][r] : -1;
    }
    __syncthreads();

    const float* Wb = W + (size_t)e * OUT * IN;

    const int tx = tid & 15;   // col group: cols tx*8 .. tx*8+7
    const int ty = tid >> 4;   // row group: rows ty*8 .. ty*8+7

    // 8x8 fp32 accumulators as 8x4 packed f32x2 (lo = even col, hi = odd col)
    unsigned long long c2[8][4];
#pragma unroll
    for (int i = 0; i < 8; i++)
#pragma unroll
        for (int j = 0; j < 4; j++) c2[i][j] = 0ull;

    // loader mapping: 4 lanes per row, 64B contiguous per row (coalesced)
    const int lm = tid >> 2;        // 0..63
    const int lk = (tid & 3) * 4;   // 0,4,8,12

    for (int k0 = 0; k0 < IN; k0 += BK) {
        // --- load A (gathered x rows) ---
#pragma unroll
        for (int rep = 0; rep < 2; rep++) {
            int m = lm + rep * 64;
            int r = ridx[m];
            float4 v = make_float4(0.f, 0.f, 0.f, 0.f);
            if (r >= 0) v = *(const float4*)(x + (size_t)r * IN + k0 + lk);
            As[lk + 0][m] = v.x; As[lk + 1][m] = v.y;
            As[lk + 2][m] = v.z; As[lk + 3][m] = v.w;
        }
        // --- load B (W[e] rows, contiguous) ---
#pragma unroll
        for (int rep = 0; rep < 2; rep++) {
            int n = lm + rep * 64;
            float4 v = *(const float4*)(Wb + (size_t)(col0 + n) * IN + k0 + lk);
            Bs[lk + 0][n] = v.x; Bs[lk + 1][n] = v.y;
            Bs[lk + 2][n] = v.z; Bs[lk + 3][n] = v.w;
        }
        __syncthreads();

#pragma unroll
        for (int kk = 0; kk < BK; kk++) {
            float4 a0 = *(const float4*)&As[kk][ty * 8];
            float4 a1 = *(const float4*)&As[kk][ty * 8 + 4];
            unsigned long long b2[4];
            const unsigned long long* bp =
                (const unsigned long long*)&Bs[kk][tx * 8];
#pragma unroll
            for (int j = 0; j < 4; j++) b2[j] = bp[j];
            float a[8] = {a0.x, a0.y, a0.z, a0.w, a1.x, a1.y, a1.z, a1.w};
#pragma unroll
            for (int i = 0; i < 8; i++) {
                unsigned int au = __float_as_uint(a[i]);
                unsigned long long a2;
                asm("mov.b64 %0, {%1, %1};" : "=l"(a2) : "r"(au));
#pragma unroll
                for (int j = 0; j < 4; j++)
                    asm("fma.rn.f32x2 %0, %1, %2, %0;"
                        : "+l"(c2[i][j]) : "l"(a2), "l"(b2[j]));
            }
        }
        __syncthreads();
    }

    // --- epilogue: out[row] += 0.5*(y + b[e]) ---
#pragma unroll
    for (int i = 0; i < 8; i++) {
        int mloc = ty * 8 + i;
        if (row0 + mloc < n_rows) {
            int r = ridx[mloc];
            float* op = out + (size_t)r * OUT + col0 + tx * 8;
            const float* bb = bias + (size_t)e * OUT + col0 + tx * 8;
#pragma unroll
            for (int j = 0; j < 4; j++) {
                float vlo = __uint_as_float((unsigned int)(c2[i][j]));
                float vhi = __uint_as_float((unsigned int)(c2[i][j] >> 32));
                atomicAdd(op + 2 * j,     0.5f * (vlo + bb[2 * j]));
                atomicAdd(op + 2 * j + 1, 0.5f * (vhi + bb[2 * j + 1]));
            }
        }
    }
}

// ---------------------------------------------------------------------------
// Launch. Inputs (metadata order): x, W, b, Ws, bs. Output: float [B, OUT].
// All launches on the default stream; everything is graph-capturable.
// ---------------------------------------------------------------------------
extern "C" void kernel_launch(void* const* d_in, const int* in_sizes, int n_in,
                              void* d_out, int out_size) {
    const float* x  = (const float*)d_in[0];
    const float* W  = (const float*)d_in[1];
    const float* b  = (const float*)d_in[2];
    const float* Ws = (const float*)d_in[3];
    const float* bs = (const float*)d_in[4];
    float* out = (float*)d_out;

    cudaMemsetAsync(out, 0, (size_t)out_size * sizeof(float));
    zero_counts_kernel<<<1, 32>>>();
    selector_kernel<<<256, 256>>>(x, Ws, bs);

    dim3 grid(OUT / BN, (BATCH + BM - 1) / BM, P);
    moe_gemm_kernel<<<grid, 256>>>(x, W, b, out);
}

// round 3
// speedup vs baseline: 1.7696x; 1.7696x over previous
#include <cuda_runtime.h>
#include <cuda_bf16.h>
#include <cstdint>

#define BATCH 8192
#define IN    2048
#define OUT   2048
#define P     8

#define BM 128
#define BN 128
#define BKC 64                 // bf16 K per chunk (128 B rows -> SW128-style xor swizzle)
#define NCHUNK (IN / BKC)      // 32

// ---- dynamic shared memory layout ----
#define SM_RIDX   0            // 128 ints
#define SM_TILE   1024
#define OFF_AHI   0            // 128 x 128B = 16 KB
#define OFF_ALO   16384
#define OFF_BHI   32768
#define OFF_BLO   49152
#define STAGE_BYTES 65536      // 64 KB per stage
#define SMEM_TOTAL (SM_TILE + 2 * STAGE_BYTES)   // 132 KB

// ---------------- device scratch (no allocations allowed) ----------------
__device__ int  g_cnt[P];
__device__ int  g_list[P][BATCH];
__device__ int4 g_sel[BATCH];                         // e1,p1,e2,p2 per sample
__device__ __nv_bfloat16 g_xhi[(size_t)BATCH * IN];
__device__ __nv_bfloat16 g_xlo[(size_t)BATCH * IN];
__device__ __nv_bfloat16 g_whi[(size_t)P * OUT * IN];
__device__ __nv_bfloat16 g_wlo[(size_t)P * OUT * IN];
__device__ float g_y[(size_t)P * BATCH * OUT];        // compacted expert outputs

// ---------------- helpers ----------------
__device__ __forceinline__ uint32_t smem_u32(const void* p) {
    uint32_t a;
    asm("{ .reg .u64 t; cvta.to.shared.u64 t, %1; cvt.u32.u64 %0, t; }"
        : "=r"(a) : "l"(p));
    return a;
}

__device__ __forceinline__ void cp16(uint32_t dst, const void* src, int sz) {
    asm volatile("cp.async.cg.shared.global [%0], [%1], 16, %2;"
                 :: "r"(dst), "l"(src), "r"(sz));
}

__device__ __forceinline__ void ldsm4(uint32_t* r, uint32_t addr) {
    asm volatile("ldmatrix.sync.aligned.m8n8.x4.shared.b16 {%0,%1,%2,%3}, [%4];"
                 : "=r"(r[0]), "=r"(r[1]), "=r"(r[2]), "=r"(r[3]) : "r"(addr));
}

__device__ __forceinline__ void mma16816(float* c, const uint32_t* a, const uint32_t* b) {
    asm volatile(
        "mma.sync.aligned.m16n8k16.row.col.f32.bf16.bf16.f32 "
        "{%0,%1,%2,%3}, {%4,%5,%6,%7}, {%8,%9}, {%0,%1,%2,%3};"
        : "+f"(c[0]), "+f"(c[1]), "+f"(c[2]), "+f"(c[3])
        : "r"(a[0]), "r"(a[1]), "r"(a[2]), "r"(a[3]), "r"(b[0]), "r"(b[1]));
}

__device__ __forceinline__ void split_pair(float a, float b,
                                           __nv_bfloat162& hi, __nv_bfloat162& lo) {
    __nv_bfloat16 ha = __float2bfloat16_rn(a), hb = __float2bfloat16_rn(b);
    __nv_bfloat16 la = __float2bfloat16_rn(a - __bfloat162float(ha));
    __nv_bfloat16 lb = __float2bfloat16_rn(b - __bfloat162float(hb));
    hi = __halves2bfloat162(ha, hb);
    lo = __halves2bfloat162(la, lb);
}

// swizzled byte offset inside a [rows][128B] tile: 16B chunk index XOR (row & 7)
__device__ __forceinline__ uint32_t sw_off(int row, int chunk) {
    return (uint32_t)(row * 128 + ((chunk ^ (row & 7)) << 4));
}

// ---------------------------------------------------------------------------
__global__ void zero_counts_kernel() {
    if (threadIdx.x < P) g_cnt[threadIdx.x] = 0;
}

// Selector: top-2 of logits (softmax monotone -> skip). Also emits bf16 hi/lo
// split of x and the per-sample (expert, slot) routing record.
__global__ void selector_kernel(const float* __restrict__ x,
                                const float* __restrict__ Ws,
                                const float* __restrict__ bs) {
    int warp = threadIdx.x >> 5;
    int lane = threadIdx.x & 31;
    int warps_per_grid = (blockDim.x >> 5) * gridDim.x;
    for (int s = blockIdx.x * (blockDim.x >> 5) + warp; s < BATCH; s += warps_per_grid) {
        const float4* xr = (const float4*)(x + (size_t)s * IN);
        __nv_bfloat162* xh = (__nv_bfloat162*)(g_xhi + (size_t)s * IN);
        __nv_bfloat162* xl = (__nv_bfloat162*)(g_xlo + (size_t)s * IN);
        float acc[P];
#pragma unroll
        for (int p = 0; p < P; p++) acc[p] = 0.f;
        for (int k4 = lane; k4 < IN / 4; k4 += 32) {
            float4 xv = xr[k4];
            __nv_bfloat162 h01, l01, h23, l23;
            split_pair(xv.x, xv.y, h01, l01);
            split_pair(xv.z, xv.w, h23, l23);
            xh[2 * k4] = h01; xh[2 * k4 + 1] = h23;
            xl[2 * k4] = l01; xl[2 * k4 + 1] = l23;
#pragma unroll
            for (int p = 0; p < P; p++) {
                float4 wv = ((const float4*)(Ws + (size_t)p * IN))[k4];
                acc[p] += xv.x * wv.x + xv.y * wv.y + xv.z * wv.z + xv.w * wv.w;
            }
        }
#pragma unroll
        for (int p = 0; p < P; p++) {
#pragma unroll
            for (int off = 16; off; off >>= 1)
                acc[p] += __shfl_xor_sync(0xffffffffu, acc[p], off);
        }
        if (lane == 0) {
            float best = -1e30f; int e1 = 0;
#pragma unroll
            for (int p = 0; p < P; p++) {
                float v = acc[p] + bs[p];
                acc[p] = v;
                if (v > best) { best = v; e1 = p; }
            }
            float sec = -1e30f; int e2 = 0;
#pragma unroll
            for (int p = 0; p < P; p++)
                if (p != e1 && acc[p] > sec) { sec = acc[p]; e2 = p; }
            int p1 = atomicAdd(&g_cnt[e1], 1);
            g_list[e1][p1] = s;
            int p2 = atomicAdd(&g_cnt[e2], 1);
            g_list[e2][p2] = s;
            g_sel[s] = make_int4(e1, p1, e2, p2);
        }
    }
}

// W -> bf16 hi/lo split
__global__ void wconv_kernel(const float* __restrict__ W) {
    size_t n4 = (size_t)P * OUT * IN / 4;
    size_t stride = (size_t)gridDim.x * blockDim.x;
    for (size_t i = (size_t)blockIdx.x * blockDim.x + threadIdx.x; i < n4; i += stride) {
        float4 v = ((const float4*)W)[i];
        __nv_bfloat162 h01, l01, h23, l23;
        split_pair(v.x, v.y, h01, l01);
        split_pair(v.z, v.w, h23, l23);
        ((__nv_bfloat162*)g_whi)[2 * i] = h01;
        ((__nv_bfloat162*)g_whi)[2 * i + 1] = h23;
        ((__nv_bfloat162*)g_wlo)[2 * i] = l01;
        ((__nv_bfloat162*)g_wlo)[2 * i + 1] = l23;
    }
}

// ---------------------------------------------------------------------------
// Grouped gather-GEMM with mma.sync (bf16, fp32 accum), 2-term split:
//   Y = Xhi*Whi^T + Xhi*Wlo^T + Xlo*Whi^T
// CTA tile 128x128, K-chunk 64, cp.async double buffering, 8 warps (4m x 2n),
// warp tile 32x64. Results go to compacted scratch g_y (no atomics).
// ---------------------------------------------------------------------------
__global__ __launch_bounds__(256, 1)
void moe_gemm_kernel() {
    const int e = blockIdx.z;
    const int n_rows = g_cnt[e];
    const int row0 = blockIdx.y * BM;
    if (row0 >= n_rows) return;
    const int col0 = blockIdx.x * BN;

    extern __shared__ char smem[];
    const uint32_t sb = smem_u32(smem);
    int* ridx = (int*)(smem + SM_RIDX);
    const int tid = threadIdx.x;
    const int lane = tid & 31;
    const int wid = tid >> 5;
    const int wm = wid & 3;      // m group: rows wm*32 .. wm*32+31
    const int wn = wid >> 2;     // n group: cols wn*64 .. wn*64+63

    if (tid < BM) {
        int r = row0 + tid;
        ridx[tid] = (r < n_rows) ? g_list[e][r] : -1;
    }
    __syncthreads();

    const __nv_bfloat16* whi = g_whi + (size_t)e * OUT * IN;
    const __nv_bfloat16* wlo = g_wlo + (size_t)e * OUT * IN;

    // stage loader: 16 cp.asyncs / thread (A row + B row, hi or lo half)
    auto load_stage = [&](int st, int c) {
        const int k0 = c * BKC;
        const uint32_t stage = sb + SM_TILE + st * STAGE_BYTES;
        const int m = tid & 127;
        {   // A
            const int r = ridx[m];
            const __nv_bfloat16* src = (tid < 128) ? g_xhi : g_xlo;
            const char* sp = (const char*)(src + (size_t)(r < 0 ? 0 : r) * IN + k0);
            const uint32_t dA = stage + ((tid < 128) ? OFF_AHI : OFF_ALO);
            const int sz = (r >= 0) ? 16 : 0;
#pragma unroll
            for (int ck = 0; ck < 8; ck++)
                cp16(dA + sw_off(m, ck), sp + ck * 16, sz);
        }
        {   // B
            const __nv_bfloat16* src = (tid < 128) ? whi : wlo;
            const char* sp = (const char*)(src + (size_t)(col0 + m) * IN + k0);
            const uint32_t dB = stage + ((tid < 128) ? OFF_BHI : OFF_BLO);
#pragma unroll
            for (int ck = 0; ck < 8; ck++)
                cp16(dB + sw_off(m, ck), sp + ck * 16, 16);
        }
        asm volatile("cp.async.commit_group;" ::: "memory");
    };

    float acc[2][8][4];
#pragma unroll
    for (int i = 0; i < 2; i++)
#pragma unroll
        for (int j = 0; j < 8; j++)
#pragma unroll
            for (int k = 0; k < 4; k++) acc[i][j][k] = 0.f;

    // per-thread ldmatrix row/chunk components
    const int a_r = lane & 15;                       // row within m16 tile
    const int a_c = lane >> 4;                       // 16B chunk within k16
    const int b_r = ((lane >> 4) & 1) * 8 + (lane & 7);
    const int b_c = (lane >> 3) & 1;

    load_stage(0, 0);
    load_stage(1, 1);

    for (int c = 0; c < NCHUNK; c++) {
        if (c + 1 < NCHUNK) asm volatile("cp.async.wait_group 1;" ::: "memory");
        else                asm volatile("cp.async.wait_group 0;" ::: "memory");
        __syncthreads();

        const uint32_t stage = sb + SM_TILE + (c & 1) * STAGE_BYTES;
#pragma unroll
        for (int ks = 0; ks < 4; ks++) {
            uint32_t ah[2][4], al[2][4], bh[4][4], bl[4][4];
#pragma unroll
            for (int i = 0; i < 2; i++) {
                int row = wm * 32 + i * 16 + a_r;
                uint32_t off = sw_off(row, 2 * ks + a_c);
                ldsm4(ah[i], stage + OFF_AHI + off);
                ldsm4(al[i], stage + OFF_ALO + off);
            }
#pragma unroll
            for (int g = 0; g < 4; g++) {
                int row = wn * 64 + g * 16 + b_r;
                uint32_t off = sw_off(row, 2 * ks + b_c);
                ldsm4(bh[g], stage + OFF_BHI + off);
                ldsm4(bl[g], stage + OFF_BLO + off);
            }
#pragma unroll
            for (int i = 0; i < 2; i++)
#pragma unroll
                for (int g = 0; g < 4; g++) {
                    mma16816(acc[i][2 * g],     ah[i], &bh[g][0]);
                    mma16816(acc[i][2 * g + 1], ah[i], &bh[g][2]);
                    mma16816(acc[i][2 * g],     ah[i], &bl[g][0]);
                    mma16816(acc[i][2 * g + 1], ah[i], &bl[g][2]);
                    mma16816(acc[i][2 * g],     al[i], &bh[g][0]);
                    mma16816(acc[i][2 * g + 1], al[i], &bh[g][2]);
                }
        }
        __syncthreads();
        if (c + 2 < NCHUNK) load_stage(c & 1, c + 2);
    }

    // epilogue: write warp tile 32x64 to compacted scratch
#pragma unroll
    for (int i = 0; i < 2; i++) {
        int mbase = wm * 32 + i * 16 + (lane >> 2);
#pragma unroll
        for (int half = 0; half < 2; half++) {
            int mloc = mbase + half * 8;
            if (row0 + mloc < n_rows) {
                float* yrow = g_y + ((size_t)e * BATCH + row0 + mloc) * OUT
                            + col0 + wn * 64 + 2 * (lane & 3);
#pragma unroll
                for (int g = 0; g < 8; g++) {
                    float2 v = make_float2(acc[i][g][2 * half], acc[i][g][2 * half + 1]);
                    *(float2*)(yrow + 8 * g) = v;
                }
            }
        }
    }
}

// Combine: out[s] = 0.5*(Y[e1][p1] + Y[e2][p2] + b[e1] + b[e2]).
__global__ void combine_kernel(const float* __restrict__ bias,
                               float* __restrict__ out) {
    const int s = blockIdx.x;
    const int4 sel = g_sel[s];
    const float4* y1 = (const float4*)(g_y + ((size_t)sel.x * BATCH + sel.y) * OUT);
    const float4* y2 = (const float4*)(g_y + ((size_t)sel.z * BATCH + sel.w) * OUT);
    const float4* b1 = (const float4*)(bias + (size_t)sel.x * OUT);
    const float4* b2 = (const float4*)(bias + (size_t)sel.z * OUT);
    float4* o = (float4*)(out + (size_t)s * OUT);
    for (int i = threadIdx.x; i < OUT / 4; i += blockDim.x) {
        float4 a = y1[i], b = y2[i], c = b1[i], d = b2[i];
        o[i] = make_float4(0.5f * (a.x + b.x + c.x + d.x),
                           0.5f * (a.y + b.y + c.y + d.y),
                           0.5f * (a.z + b.z + c.z + d.z),
                           0.5f * (a.w + b.w + c.w + d.w));
    }
}

// ---------------------------------------------------------------------------
extern "C" void kernel_launch(void* const* d_in, const int* in_sizes, int n_in,
                              void* d_out, int out_size) {
    const float* x  = (const float*)d_in[0];
    const float* W  = (const float*)d_in[1];
    const float* b  = (const float*)d_in[2];
    const float* Ws = (const float*)d_in[3];
    const float* bs = (const float*)d_in[4];
    float* out = (float*)d_out;

    static bool attr_set = false;
    if (!attr_set) {
        cudaFuncSetAttribute(moe_gemm_kernel,
                             cudaFuncAttributeMaxDynamicSharedMemorySize, SMEM_TOTAL);
        attr_set = true;
    }

    zero_counts_kernel<<<1, 32>>>();
    selector_kernel<<<256, 256>>>(x, Ws, bs);
    wconv_kernel<<<2048, 256>>>(W);

    dim3 grid(OUT / BN, BATCH / BM, P);   // (16, 64, 8); blocks beyond rows exit
    moe_gemm_kernel<<<grid, 256, SMEM_TOTAL>>>();

    combine_kernel<<<BATCH, 256>>>(b, out);
}

// round 4
// speedup vs baseline: 2.0636x; 1.1661x over previous
#include <cuda_runtime.h>
#include <cuda_bf16.h>
#include <cstdint>

#define BATCH 8192
#define IN    2048
#define OUT   2048
#define P     8

#define BM 128
#define BN 256
#define BKC 64                 // bf16 K per chunk (128 B rows, xor-swizzled)
#define NCHUNK (IN / BKC)      // 32

// ---- dynamic shared memory layout ----
#define SM_RIDX   0            // 128 ints
#define SM_TILE   1024
#define OFF_AHI   0            // 128 rows x 128B = 16 KB
#define OFF_ALO   16384
#define OFF_BHI   32768        // 256 rows x 128B = 32 KB
#define OFF_BLO   65536
#define STAGE_BYTES 98304      // 96 KB per stage
#define SMEM_TOTAL (SM_TILE + 2 * STAGE_BYTES)   // ~193 KB

// ---------------- device scratch (no allocations allowed) ----------------
__device__ int  g_cnt[P];
__device__ int  g_list[P][BATCH];
__device__ int4 g_sel[BATCH];                         // e1,p1,e2,p2 per sample
__device__ __nv_bfloat16 g_xhi[(size_t)BATCH * IN];
__device__ __nv_bfloat16 g_xlo[(size_t)BATCH * IN];
__device__ __nv_bfloat16 g_whi[(size_t)P * OUT * IN];
__device__ __nv_bfloat16 g_wlo[(size_t)P * OUT * IN];
__device__ float g_y[(size_t)P * BATCH * OUT];        // compacted expert outputs

// ---------------- helpers ----------------
__device__ __forceinline__ uint32_t smem_u32(const void* p) {
    uint32_t a;
    asm("{ .reg .u64 t; cvta.to.shared.u64 t, %1; cvt.u32.u64 %0, t; }"
        : "=r"(a) : "l"(p));
    return a;
}

__device__ __forceinline__ void cp16(uint32_t dst, const void* src, int sz) {
    asm volatile("cp.async.cg.shared.global [%0], [%1], 16, %2;"
                 :: "r"(dst), "l"(src), "r"(sz));
}

__device__ __forceinline__ void ldsm4(uint32_t* r, uint32_t addr) {
    asm volatile("ldmatrix.sync.aligned.m8n8.x4.shared.b16 {%0,%1,%2,%3}, [%4];"
                 : "=r"(r[0]), "=r"(r[1]), "=r"(r[2]), "=r"(r[3]) : "r"(addr));
}

__device__ __forceinline__ void mma16816(float* c, const uint32_t* a, const uint32_t* b) {
    asm volatile(
        "mma.sync.aligned.m16n8k16.row.col.f32.bf16.bf16.f32 "
        "{%0,%1,%2,%3}, {%4,%5,%6,%7}, {%8,%9}, {%0,%1,%2,%3};"
        : "+f"(c[0]), "+f"(c[1]), "+f"(c[2]), "+f"(c[3])
        : "r"(a[0]), "r"(a[1]), "r"(a[2]), "r"(a[3]), "r"(b[0]), "r"(b[1]));
}

__device__ __forceinline__ void split_pair(float a, float b,
                                           __nv_bfloat162& hi, __nv_bfloat162& lo) {
    __nv_bfloat16 ha = __float2bfloat16_rn(a), hb = __float2bfloat16_rn(b);
    __nv_bfloat16 la = __float2bfloat16_rn(a - __bfloat162float(ha));
    __nv_bfloat16 lb = __float2bfloat16_rn(b - __bfloat162float(hb));
    hi = __halves2bfloat162(ha, hb);
    lo = __halves2bfloat162(la, lb);
}

// swizzled byte offset inside a [rows][128B] tile: 16B chunk index XOR (row & 7)
__device__ __forceinline__ uint32_t sw_off(int row, int chunk) {
    return (uint32_t)(row * 128 + ((chunk ^ (row & 7)) << 4));
}

// ---------------------------------------------------------------------------
__global__ void zero_counts_kernel() {
    if (threadIdx.x < P) g_cnt[threadIdx.x] = 0;
}

// Selector: top-2 of logits (softmax monotone -> skip). Also emits bf16 hi/lo
// split of x and the per-sample (expert, slot) routing record.
__global__ void selector_kernel(const float* __restrict__ x,
                                const float* __restrict__ Ws,
                                const float* __restrict__ bs) {
    int warp = threadIdx.x >> 5;
    int lane = threadIdx.x & 31;
    int warps_per_grid = (blockDim.x >> 5) * gridDim.x;
    for (int s = blockIdx.x * (blockDim.x >> 5) + warp; s < BATCH; s += warps_per_grid) {
        const float4* xr = (const float4*)(x + (size_t)s * IN);
        __nv_bfloat162* xh = (__nv_bfloat162*)(g_xhi + (size_t)s * IN);
        __nv_bfloat162* xl = (__nv_bfloat162*)(g_xlo + (size_t)s * IN);
        float acc[P];
#pragma unroll
        for (int p = 0; p < P; p++) acc[p] = 0.f;
        for (int k4 = lane; k4 < IN / 4; k4 += 32) {
            float4 xv = xr[k4];
            __nv_bfloat162 h01, l01, h23, l23;
            split_pair(xv.x, xv.y, h01, l01);
            split_pair(xv.z, xv.w, h23, l23);
            xh[2 * k4] = h01; xh[2 * k4 + 1] = h23;
            xl[2 * k4] = l01; xl[2 * k4 + 1] = l23;
#pragma unroll
            for (int p = 0; p < P; p++) {
                float4 wv = ((const float4*)(Ws + (size_t)p * IN))[k4];
                acc[p] += xv.x * wv.x + xv.y * wv.y + xv.z * wv.z + xv.w * wv.w;
            }
        }
#pragma unroll
        for (int p = 0; p < P; p++) {
#pragma unroll
            for (int off = 16; off; off >>= 1)
                acc[p] += __shfl_xor_sync(0xffffffffu, acc[p], off);
        }
        if (lane == 0) {
            float best = -1e30f; int e1 = 0;
#pragma unroll
            for (int p = 0; p < P; p++) {
                float v = acc[p] + bs[p];
                acc[p] = v;
                if (v > best) { best = v; e1 = p; }
            }
            float sec = -1e30f; int e2 = 0;
#pragma unroll
            for (int p = 0; p < P; p++)
                if (p != e1 && acc[p] > sec) { sec = acc[p]; e2 = p; }
            int p1 = atomicAdd(&g_cnt[e1], 1);
            g_list[e1][p1] = s;
            int p2 = atomicAdd(&g_cnt[e2], 1);
            g_list[e2][p2] = s;
            g_sel[s] = make_int4(e1, p1, e2, p2);
        }
    }
}

// W -> bf16 hi/lo split
__global__ void wconv_kernel(const float* __restrict__ W) {
    size_t n4 = (size_t)P * OUT * IN / 4;
    size_t stride = (size_t)gridDim.x * blockDim.x;
    for (size_t i = (size_t)blockIdx.x * blockDim.x + threadIdx.x; i < n4; i += stride) {
        float4 v = ((const float4*)W)[i];
        __nv_bfloat162 h01, l01, h23, l23;
        split_pair(v.x, v.y, h01, l01);
        split_pair(v.z, v.w, h23, l23);
        ((__nv_bfloat162*)g_whi)[2 * i] = h01;
        ((__nv_bfloat162*)g_whi)[2 * i + 1] = h23;
        ((__nv_bfloat162*)g_wlo)[2 * i] = l01;
        ((__nv_bfloat162*)g_wlo)[2 * i + 1] = l23;
    }
}

// ---------------------------------------------------------------------------
// Grouped gather-GEMM with mma.sync (bf16, fp32 accum), 2-term split:
//   Y = Xhi*Whi^T + Xhi*Wlo^T + Xlo*Whi^T
// CTA tile 128x256, K-chunk 64, cp.async double buffering, 8 warps (2m x 4n),
// 64x64 warp tiles. Results go to compacted scratch g_y (no atomics).
// ---------------------------------------------------------------------------
__global__ __launch_bounds__(256, 1)
void moe_gemm_kernel() {
    const int e = blockIdx.z;
    const int n_rows = g_cnt[e];
    const int row0 = blockIdx.y * BM;
    if (row0 >= n_rows) return;
    const int col0 = blockIdx.x * BN;

    extern __shared__ char smem[];
    const uint32_t sb = smem_u32(smem);
    int* ridx = (int*)(smem + SM_RIDX);
    const int tid = threadIdx.x;
    const int lane = tid & 31;
    const int wid = tid >> 5;
    const int wm = wid & 1;      // m group: rows wm*64 .. wm*64+63
    const int wn = wid >> 1;     // n group: cols wn*64 .. wn*64+63

    if (tid < BM) {
        int r = row0 + tid;
        ridx[tid] = (r < n_rows) ? g_list[e][r] : -1;
    }
    __syncthreads();

    const __nv_bfloat16* whi = g_whi + (size_t)e * OUT * IN;
    const __nv_bfloat16* wlo = g_wlo + (size_t)e * OUT * IN;

    // stage loader: 24 cp.asyncs / thread (1 A row + 2 B rows, hi or lo half)
    auto load_stage = [&](int st, int c) {
        const int k0 = c * BKC;
        const uint32_t stage = sb + SM_TILE + st * STAGE_BYTES;
        const int m = tid & 127;
        const bool hi_half = (tid < 128);
        {   // A
            const int r = ridx[m];
            const __nv_bfloat16* src = hi_half ? g_xhi : g_xlo;
            const char* sp = (const char*)(src + (size_t)(r < 0 ? 0 : r) * IN + k0);
            const uint32_t dA = stage + (hi_half ? OFF_AHI : OFF_ALO);
            const int sz = (r >= 0) ? 16 : 0;
#pragma unroll
            for (int ck = 0; ck < 8; ck++)
                cp16(dA + sw_off(m, ck), sp + ck * 16, sz);
        }
        {   // B: rows m and m+128
            const __nv_bfloat16* src = hi_half ? whi : wlo;
            const uint32_t dB = stage + (hi_half ? OFF_BHI : OFF_BLO);
#pragma unroll
            for (int rep = 0; rep < 2; rep++) {
                const int n = m + rep * 128;
                const char* sp = (const char*)(src + (size_t)(col0 + n) * IN + k0);
#pragma unroll
                for (int ck = 0; ck < 8; ck++)
                    cp16(dB + sw_off(n, ck), sp + ck * 16, 16);
            }
        }
        asm volatile("cp.async.commit_group;" ::: "memory");
    };

    float acc[4][8][4];
#pragma unroll
    for (int i = 0; i < 4; i++)
#pragma unroll
        for (int j = 0; j < 8; j++)
#pragma unroll
            for (int k = 0; k < 4; k++) acc[i][j][k] = 0.f;

    // per-thread ldmatrix row/chunk components
    const int a_r = lane & 15;                       // row within m16 tile
    const int a_c = lane >> 4;                       // 16B chunk within k16
    const int b_r = ((lane >> 4) & 1) * 8 + (lane & 7);
    const int b_c = (lane >> 3) & 1;

    load_stage(0, 0);
    load_stage(1, 1);

    for (int c = 0; c < NCHUNK; c++) {
        if (c + 1 < NCHUNK) asm volatile("cp.async.wait_group 1;" ::: "memory");
        else                asm volatile("cp.async.wait_group 0;" ::: "memory");
        __syncthreads();

        const uint32_t stage = sb + SM_TILE + (c & 1) * STAGE_BYTES;
#pragma unroll
        for (int ks = 0; ks < 4; ks++) {
            uint32_t ah[4][4], al[4][4];
#pragma unroll
            for (int i = 0; i < 4; i++) {
                int row = wm * 64 + i * 16 + a_r;
                uint32_t off = sw_off(row, 2 * ks + a_c);
                ldsm4(ah[i], stage + OFF_AHI + off);
                ldsm4(al[i], stage + OFF_ALO + off);
            }
#pragma unroll
            for (int g = 0; g < 4; g++) {
                int row = wn * 64 + g * 16 + b_r;
                uint32_t off = sw_off(row, 2 * ks + b_c);
                uint32_t bh[4], bl[4];
                ldsm4(bh, stage + OFF_BHI + off);
                ldsm4(bl, stage + OFF_BLO + off);
#pragma unroll
                for (int i = 0; i < 4; i++) {
                    mma16816(acc[i][2 * g],     ah[i], &bh[0]);
                    mma16816(acc[i][2 * g + 1], ah[i], &bh[2]);
                    mma16816(acc[i][2 * g],     ah[i], &bl[0]);
                    mma16816(acc[i][2 * g + 1], ah[i], &bl[2]);
                    mma16816(acc[i][2 * g],     al[i], &bh[0]);
                    mma16816(acc[i][2 * g + 1], al[i], &bh[2]);
                }
            }
        }
        __syncthreads();
        if (c + 2 < NCHUNK) load_stage(c & 1, c + 2);
    }

    // epilogue: write warp tile 64x64 to compacted scratch
#pragma unroll
    for (int i = 0; i < 4; i++) {
        int mbase = wm * 64 + i * 16 + (lane >> 2);
#pragma unroll
        for (int half = 0; half < 2; half++) {
            int mloc = mbase + half * 8;
            if (row0 + mloc < n_rows) {
                float* yrow = g_y + ((size_t)e * BATCH + row0 + mloc) * OUT
                            + col0 + wn * 64 + 2 * (lane & 3);
#pragma unroll
                for (int g = 0; g < 8; g++) {
                    float2 v = make_float2(acc[i][g][2 * half], acc[i][g][2 * half + 1]);
                    *(float2*)(yrow + 8 * g) = v;
                }
            }
        }
    }
}

// Combine: out[s] = 0.5*(Y[e1][p1] + Y[e2][p2] + b[e1] + b[e2]).
__global__ void combine_kernel(const float* __restrict__ bias,
                               float* __restrict__ out) {
    const int s = blockIdx.x;
    const int4 sel = g_sel[s];
    const float4* y1 = (const float4*)(g_y + ((size_t)sel.x * BATCH + sel.y) * OUT);
    const float4* y2 = (const float4*)(g_y + ((size_t)sel.z * BATCH + sel.w) * OUT);
    const float4* b1 = (const float4*)(bias + (size_t)sel.x * OUT);
    const float4* b2 = (const float4*)(bias + (size_t)sel.z * OUT);
    float4* o = (float4*)(out + (size_t)s * OUT);
    for (int i = threadIdx.x; i < OUT / 4; i += blockDim.x) {
        float4 a = y1[i], b = y2[i], c = b1[i], d = b2[i];
        o[i] = make_float4(0.5f * (a.x + b.x + c.x + d.x),
                           0.5f * (a.y + b.y + c.y + d.y),
                           0.5f * (a.z + b.z + c.z + d.z),
                           0.5f * (a.w + b.w + c.w + d.w));
    }
}

// ---------------------------------------------------------------------------
extern "C" void kernel_launch(void* const* d_in, const int* in_sizes, int n_in,
                              void* d_out, int out_size) {
    const float* x  = (const float*)d_in[0];
    const float* W  = (const float*)d_in[1];
    const float* b  = (const float*)d_in[2];
    const float* Ws = (const float*)d_in[3];
    const float* bs = (const float*)d_in[4];
    float* out = (float*)d_out;

    static bool attr_set = false;
    if (!attr_set) {
        cudaFuncSetAttribute(moe_gemm_kernel,
                             cudaFuncAttributeMaxDynamicSharedMemorySize, SMEM_TOTAL);
        attr_set = true;
    }

    zero_counts_kernel<<<1, 32>>>();
    selector_kernel<<<256, 256>>>(x, Ws, bs);
    wconv_kernel<<<2048, 256>>>(W);

    dim3 grid(OUT / BN, BATCH / BM, P);   // (8, 64, 8); blocks beyond rows exit
    moe_gemm_kernel<<<grid, 256, SMEM_TOTAL>>>();

    combine_kernel<<<BATCH, 256>>>(b, out);
}

// round 5
// speedup vs baseline: 2.8809x; 1.3961x over previous
#include <cuda_runtime.h>
#include <cuda_bf16.h>
#include <cstdint>

#define BATCH 8192
#define IN    2048
#define OUT   2048
#define P     8

#define BM 128
#define BN 256
#define BKC 64                 // bf16 K per chunk (128 B rows, xor-swizzled)
#define NCHUNK (IN / BKC)      // 32

#define NTHREADS 288           // 8 consumer warps + 1 producer warp

// ---- dynamic shared memory layout ----
#define SM_RIDX   0            // 128 ints
#define SM_FULL   512          // 2 x 8B mbarriers
#define SM_EMPTY  528          // 2 x 8B mbarriers
#define SM_TILE   1024
#define OFF_AHI   0            // 128 rows x 128B = 16 KB
#define OFF_ALO   16384
#define OFF_BHI   32768        // 256 rows x 128B = 32 KB
#define OFF_BLO   65536
#define STAGE_BYTES 98304      // 96 KB per stage
#define SMEM_TOTAL (SM_TILE + 2 * STAGE_BYTES)   // ~193 KB

// ---------------- device scratch (no allocations allowed) ----------------
__device__ int  g_cnt[P];
__device__ int  g_list[P][BATCH];
__device__ int4 g_sel[BATCH];                         // e1,p1,e2,p2 per sample
__device__ __nv_bfloat16 g_xhi[(size_t)BATCH * IN];
__device__ __nv_bfloat16 g_xlo[(size_t)BATCH * IN];
__device__ __nv_bfloat16 g_whi[(size_t)P * OUT * IN];
__device__ __nv_bfloat16 g_wlo[(size_t)P * OUT * IN];
__device__ float g_y[(size_t)P * BATCH * OUT];        // compacted expert outputs

// ---------------- helpers ----------------
__device__ __forceinline__ uint32_t smem_u32(const void* p) {
    uint32_t a;
    asm("{ .reg .u64 t; cvta.to.shared.u64 t, %1; cvt.u32.u64 %0, t; }"
        : "=r"(a) : "l"(p));
    return a;
}

__device__ __forceinline__ void cp16(uint32_t dst, const void* src, int sz) {
    asm volatile("cp.async.cg.shared.global [%0], [%1], 16, %2;"
                 :: "r"(dst), "l"(src), "r"(sz));
}

__device__ __forceinline__ void ldsm4(uint32_t* r, uint32_t addr) {
    asm volatile("ldmatrix.sync.aligned.m8n8.x4.shared.b16 {%0,%1,%2,%3}, [%4];"
                 : "=r"(r[0]), "=r"(r[1]), "=r"(r[2]), "=r"(r[3]) : "r"(addr));
}

__device__ __forceinline__ void mma16816(float* c, const uint32_t* a, const uint32_t* b) {
    asm volatile(
        "mma.sync.aligned.m16n8k16.row.col.f32.bf16.bf16.f32 "
        "{%0,%1,%2,%3}, {%4,%5,%6,%7}, {%8,%9}, {%0,%1,%2,%3};"
        : "+f"(c[0]), "+f"(c[1]), "+f"(c[2]), "+f"(c[3])
        : "r"(a[0]), "r"(a[1]), "r"(a[2]), "r"(a[3]), "r"(b[0]), "r"(b[1]));
}

#define MBAR_INIT(addr, cnt) \
    asm volatile("mbarrier.init.shared.b64 [%0], %1;" :: "r"(addr), "r"(cnt) : "memory")

#define MBAR_ARRIVE(addr) \
    asm volatile("mbarrier.arrive.shared.b64 _, [%0];" :: "r"(addr) : "memory")

#define CPASYNC_MBAR_ARRIVE(addr) \
    asm volatile("cp.async.mbarrier.arrive.noinc.shared.b64 [%0];" :: "r"(addr) : "memory")

#define MBAR_WAIT(addr, parity) do {                                              \
    asm volatile(                                                                 \
        "{\n\t.reg .pred P1;\n\t"                                                 \
        "WAIT_%=:\n\t"                                                            \
        "mbarrier.try_wait.parity.acquire.cta.shared::cta.b64 P1, [%0], %1, 0x989680;\n\t" \
        "@P1 bra.uni DONE_%=;\n\t"                                                \
        "bra.uni WAIT_%=;\n\t"                                                    \
        "DONE_%=:\n\t}"                                                           \
        :: "r"(addr), "r"(parity) : "memory");                                    \
} while (0)

__device__ __forceinline__ void split_pair(float a, float b,
                                           __nv_bfloat162& hi, __nv_bfloat162& lo) {
    __nv_bfloat16 ha = __float2bfloat16_rn(a), hb = __float2bfloat16_rn(b);
    __nv_bfloat16 la = __float2bfloat16_rn(a - __bfloat162float(ha));
    __nv_bfloat16 lb = __float2bfloat16_rn(b - __bfloat162float(hb));
    hi = __halves2bfloat162(ha, hb);
    lo = __halves2bfloat162(la, lb);
}

// swizzled byte offset inside a [rows][128B] tile: 16B chunk index XOR (row & 7)
__device__ __forceinline__ uint32_t sw_off(int row, int chunk) {
    return (uint32_t)(row * 128 + ((chunk ^ (row & 7)) << 4));
}

// ---------------------------------------------------------------------------
__global__ void zero_counts_kernel() {
    if (threadIdx.x < P) g_cnt[threadIdx.x] = 0;
}

// Selector: top-2 of logits (softmax monotone -> skip). Also emits bf16 hi/lo
// split of x and the per-sample (expert, slot) routing record.
__global__ void selector_kernel(const float* __restrict__ x,
                                const float* __restrict__ Ws,
                                const float* __restrict__ bs) {
    int warp = threadIdx.x >> 5;
    int lane = threadIdx.x & 31;
    int warps_per_grid = (blockDim.x >> 5) * gridDim.x;
    for (int s = blockIdx.x * (blockDim.x >> 5) + warp; s < BATCH; s += warps_per_grid) {
        const float4* xr = (const float4*)(x + (size_t)s * IN);
        __nv_bfloat162* xh = (__nv_bfloat162*)(g_xhi + (size_t)s * IN);
        __nv_bfloat162* xl = (__nv_bfloat162*)(g_xlo + (size_t)s * IN);
        float acc[P];
#pragma unroll
        for (int p = 0; p < P; p++) acc[p] = 0.f;
        for (int k4 = lane; k4 < IN / 4; k4 += 32) {
            float4 xv = xr[k4];
            __nv_bfloat162 h01, l01, h23, l23;
            split_pair(xv.x, xv.y, h01, l01);
            split_pair(xv.z, xv.w, h23, l23);
            xh[2 * k4] = h01; xh[2 * k4 + 1] = h23;
            xl[2 * k4] = l01; xl[2 * k4 + 1] = l23;
#pragma unroll
            for (int p = 0; p < P; p++) {
                float4 wv = ((const float4*)(Ws + (size_t)p * IN))[k4];
                acc[p] += xv.x * wv.x + xv.y * wv.y + xv.z * wv.z + xv.w * wv.w;
            }
        }
#pragma unroll
        for (int p = 0; p < P; p++) {
#pragma unroll
            for (int off = 16; off; off >>= 1)
                acc[p] += __shfl_xor_sync(0xffffffffu, acc[p], off);
        }
        if (lane == 0) {
            float best = -1e30f; int e1 = 0;
#pragma unroll
            for (int p = 0; p < P; p++) {
                float v = acc[p] + bs[p];
                acc[p] = v;
                if (v > best) { best = v; e1 = p; }
            }
            float sec = -1e30f; int e2 = 0;
#pragma unroll
            for (int p = 0; p < P; p++)
                if (p != e1 && acc[p] > sec) { sec = acc[p]; e2 = p; }
            int p1 = atomicAdd(&g_cnt[e1], 1);
            g_list[e1][p1] = s;
            int p2 = atomicAdd(&g_cnt[e2], 1);
            g_list[e2][p2] = s;
            g_sel[s] = make_int4(e1, p1, e2, p2);
        }
    }
}

// W -> bf16 hi/lo split
__global__ void wconv_kernel(const float* __restrict__ W) {
    size_t n4 = (size_t)P * OUT * IN / 4;
    size_t stride = (size_t)gridDim.x * blockDim.x;
    for (size_t i = (size_t)blockIdx.x * blockDim.x + threadIdx.x; i < n4; i += stride) {
        float4 v = ((const float4*)W)[i];
        __nv_bfloat162 h01, l01, h23, l23;
        split_pair(v.x, v.y, h01, l01);
        split_pair(v.z, v.w, h23, l23);
        ((__nv_bfloat162*)g_whi)[2 * i] = h01;
        ((__nv_bfloat162*)g_whi)[2 * i + 1] = h23;
        ((__nv_bfloat162*)g_wlo)[2 * i] = l01;
        ((__nv_bfloat162*)g_wlo)[2 * i + 1] = l23;
    }
}

// ---------------------------------------------------------------------------
// Warp-specialized grouped gather-GEMM (bf16 mma.sync, fp32 accum, 2-term
// split: Y = Xhi*Whi^T + Xhi*Wlo^T + Xlo*Whi^T).
// 8 consumer warps (64x64 tiles of a 128x256 CTA tile) + 1 producer warp
// issuing all cp.asyncs. mbarrier full/empty ring, 2 stages, no __syncthreads
// in the mainloop -> consumer warps drift instead of lockstepping.
// ---------------------------------------------------------------------------
__global__ __launch_bounds__(NTHREADS, 1)
void moe_gemm_kernel() {
    const int e = blockIdx.z;
    const int n_rows = g_cnt[e];
    const int row0 = blockIdx.y * BM;
    if (row0 >= n_rows) return;
    const int col0 = blockIdx.x * BN;

    extern __shared__ char smem[];
    const uint32_t sb = smem_u32(smem);
    int* ridx = (int*)(smem + SM_RIDX);
    const int tid = threadIdx.x;
    const int lane = tid & 31;
    const int wid = tid >> 5;

    if (tid == 0) {
#pragma unroll
        for (int s = 0; s < 2; s++) {
            MBAR_INIT(sb + SM_FULL + 8 * s, 32);   // 32 producer lanes
            MBAR_INIT(sb + SM_EMPTY + 8 * s, 8);   // 8 consumer warps
        }
    }
    if (tid < BM) {
        int r = row0 + tid;
        ridx[tid] = (r < n_rows) ? g_list[e][r] : -1;
    }
    __syncthreads();

    const __nv_bfloat16* whi = g_whi + (size_t)e * OUT * IN;
    const __nv_bfloat16* wlo = g_wlo + (size_t)e * OUT * IN;

    if (wid == 8) {
        // ------------------- producer warp -------------------
        const int ck = lane & 7;           // 16B chunk in 128B row
        const int rg = lane >> 3;          // 0..3
        int ph_empty[2] = {0, 0};
        for (int c = 0; c < NCHUNK; c++) {
            const int st = c & 1;
            if (c >= 2) {
                MBAR_WAIT(sb + SM_EMPTY + 8 * st, ph_empty[st]);
                ph_empty[st] ^= 1;
            }
            const int k0 = c * BKC;
            const uint32_t stage = sb + SM_TILE + st * STAGE_BYTES;
            // A hi+lo: 128 rows each, gathered
#pragma unroll 4
            for (int i = 0; i < 32; i++) {
                const int m = i * 4 + rg;
                const int r = ridx[m];
                const size_t off = ((size_t)(r < 0 ? 0 : r) * IN + k0) * 2 + ck * 16;
                const int sz = (r >= 0) ? 16 : 0;
                const uint32_t so = sw_off(m, ck);
                cp16(stage + OFF_AHI + so, (const char*)g_xhi + off, sz);
                cp16(stage + OFF_ALO + so, (const char*)g_xlo + off, sz);
            }
            // B hi+lo: 256 rows each, contiguous
#pragma unroll 4
            for (int i = 0; i < 64; i++) {
                const int n = i * 4 + rg;
                const size_t off = ((size_t)(col0 + n) * IN + k0) * 2 + ck * 16;
                const uint32_t so = sw_off(n, ck);
                cp16(stage + OFF_BHI + so, (const char*)whi + off, 16);
                cp16(stage + OFF_BLO + so, (const char*)wlo + off, 16);
            }
            CPASYNC_MBAR_ARRIVE(sb + SM_FULL + 8 * st);
        }
        return;
    }

    // ------------------- consumer warps -------------------
    const int wm = wid & 1;      // m group: rows wm*64 .. wm*64+63
    const int wn = wid >> 1;     // n group: cols wn*64 .. wn*64+63

    float acc[4][8][4];
#pragma unroll
    for (int i = 0; i < 4; i++)
#pragma unroll
        for (int j = 0; j < 8; j++)
#pragma unroll
            for (int k = 0; k < 4; k++) acc[i][j][k] = 0.f;

    const int a_r = lane & 15;
    const int a_c = lane >> 4;
    const int b_r = ((lane >> 4) & 1) * 8 + (lane & 7);
    const int b_c = (lane >> 3) & 1;

    int ph_full[2] = {0, 0};
    for (int c = 0; c < NCHUNK; c++) {
        const int st = c & 1;
        MBAR_WAIT(sb + SM_FULL + 8 * st, ph_full[st]);
        ph_full[st] ^= 1;

        const uint32_t stage = sb + SM_TILE + st * STAGE_BYTES;
#pragma unroll
        for (int ks = 0; ks < 4; ks++) {
            uint32_t ah[4][4], al[4][4];
#pragma unroll
            for (int i = 0; i < 4; i++) {
                int row = wm * 64 + i * 16 + a_r;
                uint32_t off = sw_off(row, 2 * ks + a_c);
                ldsm4(ah[i], stage + OFF_AHI + off);
                ldsm4(al[i], stage + OFF_ALO + off);
            }
#pragma unroll
            for (int g = 0; g < 4; g++) {
                int row = wn * 64 + g * 16 + b_r;
                uint32_t off = sw_off(row, 2 * ks + b_c);
                uint32_t bh[4], bl[4];
                ldsm4(bh, stage + OFF_BHI + off);
                ldsm4(bl, stage + OFF_BLO + off);
#pragma unroll
                for (int i = 0; i < 4; i++) {
                    mma16816(acc[i][2 * g],     ah[i], &bh[0]);
                    mma16816(acc[i][2 * g + 1], ah[i], &bh[2]);
                    mma16816(acc[i][2 * g],     ah[i], &bl[0]);
                    mma16816(acc[i][2 * g + 1], ah[i], &bl[2]);
                    mma16816(acc[i][2 * g],     al[i], &bh[0]);
                    mma16816(acc[i][2 * g + 1], al[i], &bh[2]);
                }
            }
        }
        __syncwarp();
        if (lane == 0) MBAR_ARRIVE(sb + SM_EMPTY + 8 * st);
    }

    // epilogue: write warp tile 64x64 to compacted scratch
#pragma unroll
    for (int i = 0; i < 4; i++) {
        int mbase = wm * 64 + i * 16 + (lane >> 2);
#pragma unroll
        for (int half = 0; half < 2; half++) {
            int mloc = mbase + half * 8;
            if (row0 + mloc < n_rows) {
                float* yrow = g_y + ((size_t)e * BATCH + row0 + mloc) * OUT
                            + col0 + wn * 64 + 2 * (lane & 3);
#pragma unroll
                for (int g = 0; g < 8; g++) {
                    float2 v = make_float2(acc[i][g][2 * half], acc[i][g][2 * half + 1]);
                    *(float2*)(yrow + 8 * g) = v;
                }
            }
        }
    }
}

// Combine: out[s] = 0.5*(Y[e1][p1] + Y[e2][p2] + b[e1] + b[e2]).
__global__ void combine_kernel(const float* __restrict__ bias,
                               float* __restrict__ out) {
    const int s = blockIdx.x;
    const int4 sel = g_sel[s];
    const float4* y1 = (const float4*)(g_y + ((size_t)sel.x * BATCH + sel.y) * OUT);
    const float4* y2 = (const float4*)(g_y + ((size_t)sel.z * BATCH + sel.w) * OUT);
    const float4* b1 = (const float4*)(bias + (size_t)sel.x * OUT);
    const float4* b2 = (const float4*)(bias + (size_t)sel.z * OUT);
    float4* o = (float4*)(out + (size_t)s * OUT);
    for (int i = threadIdx.x; i < OUT / 4; i += blockDim.x) {
        float4 a = y1[i], b = y2[i], c = b1[i], d = b2[i];
        o[i] = make_float4(0.5f * (a.x + b.x + c.x + d.x),
                           0.5f * (a.y + b.y + c.y + d.y),
                           0.5f * (a.z + b.z + c.z + d.z),
                           0.5f * (a.w + b.w + c.w + d.w));
    }
}

// ---------------------------------------------------------------------------
extern "C" void kernel_launch(void* const* d_in, const int* in_sizes, int n_in,
                              void* d_out, int out_size) {
    const float* x  = (const float*)d_in[0];
    const float* W  = (const float*)d_in[1];
    const float* b  = (const float*)d_in[2];
    const float* Ws = (const float*)d_in[3];
    const float* bs = (const float*)d_in[4];
    float* out = (float*)d_out;

    static bool attr_set = false;
    if (!attr_set) {
        cudaFuncSetAttribute(moe_gemm_kernel,
                             cudaFuncAttributeMaxDynamicSharedMemorySize, SMEM_TOTAL);
        attr_set = true;
    }

    zero_counts_kernel<<<1, 32>>>();
    selector_kernel<<<256, 256>>>(x, Ws, bs);
    wconv_kernel<<<2048, 256>>>(W);

    dim3 grid(OUT / BN, BATCH / BM, P);   // (8, 64, 8); blocks beyond rows exit
    moe_gemm_kernel<<<grid, NTHREADS, SMEM_TOTAL>>>();

    combine_kernel<<<BATCH, 256>>>(b, out);
}

// round 6
// speedup vs baseline: 6.8863x; 2.3903x over previous
#include <cuda_runtime.h>
#include <cuda_fp16.h>
#include <cstdint>

#define BATCH 8192
#define IN    2048
#define OUT   2048
#define P     8

#define BM 128
#define BN 256
#define BKC 64                 // fp16 K per chunk (128 B rows, xor-swizzled)
#define NCHUNK (IN / BKC)      // 32
#define NSTAGE 4

#define NTHREADS 384           // 8 consumer warps + 4 producer warps

// ---- dynamic shared memory layout ----
#define SM_RIDX   0            // 128 ints
#define SM_FULL   512          // 4 x 8B mbarriers
#define SM_EMPTY  576          // 4 x 8B mbarriers
#define SM_TILE   1024
#define OFF_A     0            // 128 rows x 128B = 16 KB
#define OFF_B     16384        // 256 rows x 128B = 32 KB
#define STAGE_BYTES 49152      // 48 KB per stage
#define SMEM_TOTAL (SM_TILE + NSTAGE * STAGE_BYTES)   // 197632 B

// ---------------- device scratch (no allocations allowed) ----------------
__device__ int  g_cnt[P];
__device__ int  g_list[P][BATCH];
__device__ int4 g_sel[BATCH];                      // e1,p1,e2,p2 per sample
__device__ __half g_xh[(size_t)BATCH * IN];        // 32 MB
__device__ __half g_wh[(size_t)P * OUT * IN];      // 64 MB
__device__ float g_y[(size_t)P * BATCH * OUT];     // compacted expert outputs

// ---------------- helpers ----------------
__device__ __forceinline__ uint32_t smem_u32(const void* p) {
    uint32_t a;
    asm("{ .reg .u64 t; cvta.to.shared.u64 t, %1; cvt.u32.u64 %0, t; }"
        : "=r"(a) : "l"(p));
    return a;
}

__device__ __forceinline__ void cp16(uint32_t dst, const void* src, int sz) {
    asm volatile("cp.async.cg.shared.global [%0], [%1], 16, %2;"
                 :: "r"(dst), "l"(src), "r"(sz));
}

__device__ __forceinline__ void ldsm4(uint32_t* r, uint32_t addr) {
    asm volatile("ldmatrix.sync.aligned.m8n8.x4.shared.b16 {%0,%1,%2,%3}, [%4];"
                 : "=r"(r[0]), "=r"(r[1]), "=r"(r[2]), "=r"(r[3]) : "r"(addr));
}

__device__ __forceinline__ void mma16816(float* c, const uint32_t* a, const uint32_t* b) {
    asm volatile(
        "mma.sync.aligned.m16n8k16.row.col.f32.f16.f16.f32 "
        "{%0,%1,%2,%3}, {%4,%5,%6,%7}, {%8,%9}, {%0,%1,%2,%3};"
        : "+f"(c[0]), "+f"(c[1]), "+f"(c[2]), "+f"(c[3])
        : "r"(a[0]), "r"(a[1]), "r"(a[2]), "r"(a[3]), "r"(b[0]), "r"(b[1]));
}

#define MBAR_INIT(addr, cnt) \
    asm volatile("mbarrier.init.shared.b64 [%0], %1;" :: "r"(addr), "r"(cnt) : "memory")

#define MBAR_ARRIVE(addr) \
    asm volatile("mbarrier.arrive.shared.b64 _, [%0];" :: "r"(addr) : "memory")

#define CPASYNC_MBAR_ARRIVE(addr) \
    asm volatile("cp.async.mbarrier.arrive.noinc.shared.b64 [%0];" :: "r"(addr) : "memory")

#define MBAR_WAIT(addr, parity) do {                                              \
    asm volatile(                                                                 \
        "{\n\t.reg .pred P1;\n\t"                                                 \
        "WAIT_%=:\n\t"                                                            \
        "mbarrier.try_wait.parity.acquire.cta.shared::cta.b64 P1, [%0], %1, 0x989680;\n\t" \
        "@P1 bra.uni DONE_%=;\n\t"                                                \
        "bra.uni WAIT_%=;\n\t"                                                    \
        "DONE_%=:\n\t}"                                                           \
        :: "r"(addr), "r"(parity) : "memory");                                    \
} while (0)

// swizzled byte offset inside a [rows][128B] tile: 16B chunk index XOR (row & 7)
__device__ __forceinline__ uint32_t sw_off(int row, int chunk) {
    return (uint32_t)(row * 128 + ((chunk ^ (row & 7)) << 4));
}

// ---------------------------------------------------------------------------
// W -> fp16 (also zeroes routing counters; runs before selector in stream order)
__global__ void wconv_kernel(const float* __restrict__ W) {
    if (blockIdx.x == 0 && threadIdx.x < P) g_cnt[threadIdx.x] = 0;
    size_t n4 = (size_t)P * OUT * IN / 4;
    size_t stride = (size_t)gridDim.x * blockDim.x;
    for (size_t i = (size_t)blockIdx.x * blockDim.x + threadIdx.x; i < n4; i += stride) {
        float4 v = ((const float4*)W)[i];
        __half2 h01 = __floats2half2_rn(v.x, v.y);
        __half2 h23 = __floats2half2_rn(v.z, v.w);
        ((__half2*)g_wh)[2 * i] = h01;
        ((__half2*)g_wh)[2 * i + 1] = h23;
    }
}

// Selector: top-2 of logits (softmax monotone -> skip). Also emits fp16 x and
// the per-sample (expert, slot) routing record.
__global__ void selector_kernel(const float* __restrict__ x,
                                const float* __restrict__ Ws,
                                const float* __restrict__ bs) {
    int warp = threadIdx.x >> 5;
    int lane = threadIdx.x & 31;
    int warps_per_grid = (blockDim.x >> 5) * gridDim.x;
    for (int s = blockIdx.x * (blockDim.x >> 5) + warp; s < BATCH; s += warps_per_grid) {
        const float4* xr = (const float4*)(x + (size_t)s * IN);
        __half2* xh = (__half2*)(g_xh + (size_t)s * IN);
        float acc[P];
#pragma unroll
        for (int p = 0; p < P; p++) acc[p] = 0.f;
        for (int k4 = lane; k4 < IN / 4; k4 += 32) {
            float4 xv = xr[k4];
            xh[2 * k4]     = __floats2half2_rn(xv.x, xv.y);
            xh[2 * k4 + 1] = __floats2half2_rn(xv.z, xv.w);
#pragma unroll
            for (int p = 0; p < P; p++) {
                float4 wv = ((const float4*)(Ws + (size_t)p * IN))[k4];
                acc[p] += xv.x * wv.x + xv.y * wv.y + xv.z * wv.z + xv.w * wv.w;
            }
        }
#pragma unroll
        for (int p = 0; p < P; p++) {
#pragma unroll
            for (int off = 16; off; off >>= 1)
                acc[p] += __shfl_xor_sync(0xffffffffu, acc[p], off);
        }
        if (lane == 0) {
            float best = -1e30f; int e1 = 0;
#pragma unroll
            for (int p = 0; p < P; p++) {
                float v = acc[p] + bs[p];
                acc[p] = v;
                if (v > best) { best = v; e1 = p; }
            }
            float sec = -1e30f; int e2 = 0;
#pragma unroll
            for (int p = 0; p < P; p++)
                if (p != e1 && acc[p] > sec) { sec = acc[p]; e2 = p; }
            int p1 = atomicAdd(&g_cnt[e1], 1);
            g_list[e1][p1] = s;
            int p2 = atomicAdd(&g_cnt[e2], 1);
            g_list[e2][p2] = s;
            g_sel[s] = make_int4(e1, p1, e2, p2);
        }
    }
}

// ---------------------------------------------------------------------------
// Warp-specialized grouped gather-GEMM, single-pass fp16 mma.sync (fp32 acc).
// 8 consumer warps (64x64 tiles of 128x256) + 4 producer warps (one per SMSP,
// 24 cp.asyncs each per chunk). 4-stage mbarrier ring, no mainloop barriers.
// ---------------------------------------------------------------------------
__global__ __launch_bounds__(NTHREADS, 1)
void moe_gemm_kernel() {
    const int e = blockIdx.z;
    const int n_rows = g_cnt[e];
    const int row0 = blockIdx.y * BM;
    if (row0 >= n_rows) return;
    const int col0 = blockIdx.x * BN;

    extern __shared__ char smem[];
    const uint32_t sb = smem_u32(smem);
    int* ridx = (int*)(smem + SM_RIDX);
    const int tid = threadIdx.x;
    const int lane = tid & 31;
    const int wid = tid >> 5;

    if (tid == 0) {
#pragma unroll
        for (int s = 0; s < NSTAGE; s++) {
            MBAR_INIT(sb + SM_FULL + 8 * s, 128);  // 128 producer lanes
            MBAR_INIT(sb + SM_EMPTY + 8 * s, 8);   // 8 consumer warps
        }
    }
    if (tid < BM) {
        int r = row0 + tid;
        ridx[tid] = (r < n_rows) ? g_list[e][r] : -1;
    }
    __syncthreads();

    const __half* wh = g_wh + (size_t)e * OUT * IN;

    if (wid >= 8) {
        // ------------------- 4 producer warps -------------------
        const int plane = (wid - 8) * 32 + lane;   // 0..127
        const int ck = plane & 7;                  // 16B chunk in 128B row
        const int rg = plane >> 3;                 // 0..15
        int ph_empty[NSTAGE] = {0, 0, 0, 0};
        for (int c = 0; c < NCHUNK; c++) {
            const int st = c & (NSTAGE - 1);
            if (c >= NSTAGE) {
                MBAR_WAIT(sb + SM_EMPTY + 8 * st, ph_empty[st]);
                ph_empty[st] ^= 1;
            }
            const int k0 = c * BKC;
            const uint32_t stage = sb + SM_TILE + st * STAGE_BYTES;
            // A: 128 gathered rows, 8 per lane
#pragma unroll
            for (int i = 0; i < 8; i++) {
                const int m = i * 16 + rg;
                const int r = ridx[m];
                const size_t off = ((size_t)(r < 0 ? 0 : r) * IN + k0) * 2 + ck * 16;
                cp16(stage + OFF_A + sw_off(m, ck), (const char*)g_xh + off,
                     (r >= 0) ? 16 : 0);
            }
            // B: 256 contiguous rows, 16 per lane
#pragma unroll
            for (int i = 0; i < 16; i++) {
                const int n = i * 16 + rg;
                const size_t off = ((size_t)(col0 + n) * IN + k0) * 2 + ck * 16;
                cp16(stage + OFF_B + sw_off(n, ck), (const char*)wh + off, 16);
            }
            CPASYNC_MBAR_ARRIVE(sb + SM_FULL + 8 * st);
        }
        return;
    }

    // ------------------- consumer warps -------------------
    const int wm = wid & 1;      // m group: rows wm*64 .. wm*64+63
    const int wn = wid >> 1;     // n group: cols wn*64 .. wn*64+63

    float acc[4][8][4];
#pragma unroll
    for (int i = 0; i < 4; i++)
#pragma unroll
        for (int j = 0; j < 8; j++)
#pragma unroll
            for (int k = 0; k < 4; k++) acc[i][j][k] = 0.f;

    const int a_r = lane & 15;
    const int a_c = lane >> 4;
    const int b_r = ((lane >> 4) & 1) * 8 + (lane & 7);
    const int b_c = (lane >> 3) & 1;

    int ph_full[NSTAGE] = {0, 0, 0, 0};
    for (int c = 0; c < NCHUNK; c++) {
        const int st = c & (NSTAGE - 1);
        MBAR_WAIT(sb + SM_FULL + 8 * st, ph_full[st]);
        ph_full[st] ^= 1;

        const uint32_t stage = sb + SM_TILE + st * STAGE_BYTES;
#pragma unroll
        for (int ks = 0; ks < 4; ks++) {
            uint32_t ah[4][4];
#pragma unroll
            for (int i = 0; i < 4; i++) {
                int row = wm * 64 + i * 16 + a_r;
                ldsm4(ah[i], stage + OFF_A + sw_off(row, 2 * ks + a_c));
            }
#pragma unroll
            for (int g = 0; g < 4; g++) {
                int row = wn * 64 + g * 16 + b_r;
                uint32_t bf[4];
                ldsm4(bf, stage + OFF_B + sw_off(row, 2 * ks + b_c));
#pragma unroll
                for (int i = 0; i < 4; i++) {
                    mma16816(acc[i][2 * g],     ah[i], &bf[0]);
                    mma16816(acc[i][2 * g + 1], ah[i], &bf[2]);
                }
            }
        }
        __syncwarp();
        if (lane == 0) MBAR_ARRIVE(sb + SM_EMPTY + 8 * st);
    }

    // epilogue: write warp tile 64x64 to compacted scratch
#pragma unroll
    for (int i = 0; i < 4; i++) {
        int mbase = wm * 64 + i * 16 + (lane >> 2);
#pragma unroll
        for (int half = 0; half < 2; half++) {
            int mloc = mbase + half * 8;
            if (row0 + mloc < n_rows) {
                float* yrow = g_y + ((size_t)e * BATCH + row0 + mloc) * OUT
                            + col0 + wn * 64 + 2 * (lane & 3);
#pragma unroll
                for (int g = 0; g < 8; g++) {
                    float2 v = make_float2(acc[i][g][2 * half], acc[i][g][2 * half + 1]);
                    *(float2*)(yrow + 8 * g) = v;
                }
            }
        }
    }
}

// Combine: out[s] = 0.5*(Y[e1][p1] + Y[e2][p2] + b[e1] + b[e2]).
__global__ void combine_kernel(const float* __restrict__ bias,
                               float* __restrict__ out) {
    const int s = blockIdx.x;
    const int4 sel = g_sel[s];
    const float4* y1 = (const float4*)(g_y + ((size_t)sel.x * BATCH + sel.y) * OUT);
    const float4* y2 = (const float4*)(g_y + ((size_t)sel.z * BATCH + sel.w) * OUT);
    const float4* b1 = (const float4*)(bias + (size_t)sel.x * OUT);
    const float4* b2 = (const float4*)(bias + (size_t)sel.z * OUT);
    float4* o = (float4*)(out + (size_t)s * OUT);
    for (int i = threadIdx.x; i < OUT / 4; i += blockDim.x) {
        float4 a = y1[i], b = y2[i], c = b1[i], d = b2[i];
        o[i] = make_float4(0.5f * (a.x + b.x + c.x + d.x),
                           0.5f * (a.y + b.y + c.y + d.y),
                           0.5f * (a.z + b.z + c.z + d.z),
                           0.5f * (a.w + b.w + c.w + d.w));
    }
}

// ---------------------------------------------------------------------------
extern "C" void kernel_launch(void* const* d_in, const int* in_sizes, int n_in,
                              void* d_out, int out_size) {
    const float* x  = (const float*)d_in[0];
    const float* W  = (const float*)d_in[1];
    const float* b  = (const float*)d_in[2];
    const float* Ws = (const float*)d_in[3];
    const float* bs = (const float*)d_in[4];
    float* out = (float*)d_out;

    static bool attr_set = false;
    if (!attr_set) {
        cudaFuncSetAttribute(moe_gemm_kernel,
                             cudaFuncAttributeMaxDynamicSharedMemorySize, SMEM_TOTAL);
        attr_set = true;
    }

    wconv_kernel<<<2048, 256>>>(W);          // also zeroes g_cnt (block 0)
    selector_kernel<<<256, 256>>>(x, Ws, bs);

    dim3 grid(OUT / BN, BATCH / BM, P);      // (8, 64, 8); blocks beyond rows exit
    moe_gemm_kernel<<<grid, NTHREADS, SMEM_TOTAL>>>();

    combine_kernel<<<BATCH, 256>>>(b, out);
}